// round 1
// baseline (speedup 1.0000x reference)
#include <cuda_runtime.h>

#define DI __device__ __forceinline__

#define B_   16
#define S_   256
#define D_   256
#define H_   128
#define DK_  64
#define SIN_ 512
#define UN_  1024
#define M_   4096

__device__ float g_XT[B_ * DK_ * S_];   // [b][k][l]
__device__ float g_YT[M_ * DK_];        // [(s*B+b)][k]
__device__ float g_IN[M_ * SIN_];       // [(s*B+b)][0:256]=out, [256:512]=pools
__device__ float g_U [M_ * UN_];        // [(s*B+b)][dir*512 + slice*128 + h]

DI float tanh_acc(float x) {
    float e = __expf(2.0f * x);
    return 1.0f - __fdividef(2.0f, e + 1.0f);
}
DI float sigm(float x) {
    return __fdividef(1.0f, 1.0f + __expf(-x));
}

__global__ void k_init(const float* __restrict__ x) {
    int i = blockIdx.x * blockDim.x + threadIdx.x;
    int d  = i & (D_ - 1);
    int sb = i >> 8;
    int b  = sb & (B_ - 1);
    int s  = sb >> 4;
    g_IN[(s * B_ + b) * SIN_ + d] = x[(b * S_ + s) * D_ + d];
}

__global__ void __launch_bounds__(256) k_projXT(const float* __restrict__ x,
                                                const int* __restrict__ actions,
                                                const float* __restrict__ w1,
                                                const float* __restrict__ b1) {
    int b  = blockIdx.y;
    int l0 = blockIdx.x * 64;
    int a  = actions[b];
    const float* W = w1 + a * D_ * DK_;
    const float* X = x + (b * S_ + l0) * D_;
    __shared__ float Xs[64][64];
    __shared__ float Ws[64][64];
    int tid = threadIdx.x;
    int tx = tid & 15, ty = tid >> 4;
    float acc[4][4] = {};
    for (int dc = 0; dc < 4; dc++) {
        #pragma unroll
        for (int p = 0; p < 4; p++) {
            int r  = (tid >> 4) + p * 16;
            int cc = (tid & 15) * 4;
            *(float4*)&Xs[r][cc] = *(const float4*)(X + r * D_ + dc * 64 + cc);
            *(float4*)&Ws[r][cc] = *(const float4*)(W + (dc * 64 + r) * DK_ + cc);
        }
        __syncthreads();
        #pragma unroll
        for (int dd = 0; dd < 64; dd++) {
            float av[4], bv[4];
            #pragma unroll
            for (int i = 0; i < 4; i++) av[i] = Xs[ty * 4 + i][dd];
            *(float4*)bv = *(float4*)&Ws[dd][tx * 4];
            #pragma unroll
            for (int i = 0; i < 4; i++)
                #pragma unroll
                for (int j = 0; j < 4; j++) acc[i][j] += av[i] * bv[j];
        }
        __syncthreads();
    }
    #pragma unroll
    for (int j = 0; j < 4; j++) {
        int k = tx * 4 + j;
        float bb = b1[a * DK_ + k];
        #pragma unroll
        for (int i = 0; i < 4; i++) {
            int l = l0 + ty * 4 + i;
            g_XT[(b * DK_ + k) * S_ + l] = acc[i][j] + bb;
        }
    }
}

__global__ void __launch_bounds__(256) k_projYT(const int* __restrict__ actions,
                                                const float* __restrict__ w2,
                                                const float* __restrict__ b2) {
    int b  = blockIdx.y;
    int s0 = blockIdx.x * 64;
    int a  = actions[b];
    const float* W = w2 + a * D_ * DK_;
    __shared__ float Xs[64][64];
    __shared__ float Ws[64][64];
    int tid = threadIdx.x;
    int tx = tid & 15, ty = tid >> 4;
    float acc[4][4] = {};
    for (int dc = 0; dc < 4; dc++) {
        #pragma unroll
        for (int p = 0; p < 4; p++) {
            int r  = (tid >> 4) + p * 16;
            int cc = (tid & 15) * 4;
            *(float4*)&Xs[r][cc] =
                *(const float4*)(&g_IN[((s0 + r) * B_ + b) * SIN_ + dc * 64 + cc]);
            *(float4*)&Ws[r][cc] = *(const float4*)(W + (dc * 64 + r) * DK_ + cc);
        }
        __syncthreads();
        #pragma unroll
        for (int dd = 0; dd < 64; dd++) {
            float av[4], bv[4];
            #pragma unroll
            for (int i = 0; i < 4; i++) av[i] = Xs[ty * 4 + i][dd];
            *(float4*)bv = *(float4*)&Ws[dd][tx * 4];
            #pragma unroll
            for (int i = 0; i < 4; i++)
                #pragma unroll
                for (int j = 0; j < 4; j++) acc[i][j] += av[i] * bv[j];
        }
        __syncthreads();
    }
    #pragma unroll
    for (int j = 0; j < 4; j++) {
        int k = tx * 4 + j;
        float bb = b2[a * DK_ + k];
        #pragma unroll
        for (int i = 0; i < 4; i++) {
            int s = s0 + ty * 4 + i;
            g_YT[(s * B_ + b) * DK_ + k] = acc[i][j] + bb;
        }
    }
}

__global__ void __launch_bounds__(256) k_attn(const float* __restrict__ x,
                                              const int* __restrict__ actions,
                                              const float* __restrict__ v) {
    const int G = 16;
    int b  = blockIdx.x & (B_ - 1);
    int s0 = (blockIdx.x >> 4) * G;
    int tid = threadIdx.x;
    int a = actions[b];
    __shared__ __align__(16) float yt[G][DK_];
    __shared__ __align__(16) float att[G][S_];
    __shared__ float vv[DK_];
    __shared__ float inv[G];
    for (int i = tid; i < G * DK_; i += 256) {
        int g = i >> 6, k = i & 63;
        yt[g][k] = g_YT[((s0 + g) * B_ + b) * DK_ + k];
    }
    if (tid < DK_) vv[tid] = v[a * DK_ + tid];
    __syncthreads();

    const float* xtp = g_XT + b * DK_ * S_;
    float sc[G];
    #pragma unroll
    for (int g = 0; g < G; g++) sc[g] = 0.0f;
    int l = tid;
    for (int k = 0; k < DK_; k++) {
        float xt = xtp[k * S_ + l];
        float vk = vv[k];
        #pragma unroll
        for (int g = 0; g < G; g++)
            sc[g] += tanh_acc(xt + yt[g][k]) * vk;
    }
    #pragma unroll
    for (int g = 0; g < G; g++) att[g][l] = sc[g];
    __syncthreads();

    int w = tid >> 5, lane = tid & 31;
    #pragma unroll
    for (int gg = 0; gg < 2; gg++) {
        int g = w * 2 + gg;
        float m = -1e30f;
        #pragma unroll
        for (int j = 0; j < 8; j++) m = fmaxf(m, att[g][lane * 8 + j]);
        #pragma unroll
        for (int o = 16; o > 0; o >>= 1) m = fmaxf(m, __shfl_xor_sync(0xffffffffu, m, o));
        float ssum = 0.0f;
        #pragma unroll
        for (int j = 0; j < 8; j++) {
            float e = __expf(att[g][lane * 8 + j] - m);
            att[g][lane * 8 + j] = e;
            ssum += e;
        }
        #pragma unroll
        for (int o = 16; o > 0; o >>= 1) ssum += __shfl_xor_sync(0xffffffffu, ssum, o);
        if (lane == 0) inv[g] = __fdividef(1.0f, ssum);
    }
    __syncthreads();

    float acc[G];
    #pragma unroll
    for (int g = 0; g < G; g++) acc[g] = 0.0f;
    const float* xb = x + b * S_ * D_;
    int d = tid;
    for (int l2 = 0; l2 < S_; l2 += 4) {
        float xv0 = xb[(l2 + 0) * D_ + d];
        float xv1 = xb[(l2 + 1) * D_ + d];
        float xv2 = xb[(l2 + 2) * D_ + d];
        float xv3 = xb[(l2 + 3) * D_ + d];
        #pragma unroll
        for (int g = 0; g < G; g++) {
            float4 av = *reinterpret_cast<const float4*>(&att[g][l2]);
            acc[g] += av.x * xv0 + av.y * xv1 + av.z * xv2 + av.w * xv3;
        }
    }
    #pragma unroll
    for (int g = 0; g < G; g++)
        g_IN[((s0 + g) * B_ + b) * SIN_ + D_ + d] = acc[g] * inv[g];
}

__global__ void __launch_bounds__(256, 2) k_sgemm(const float* __restrict__ wf,
                                                  const float* __restrict__ wb) {
    const int BM = 128, BN = 128, BK = 8;
    __shared__ float As[2][BK][BM];
    __shared__ float Bs[2][BK][BN];
    int bn = blockIdx.x, bm = blockIdx.y;
    const float* W = (bn < 4) ? wf : wb;
    int col0 = (bn & 3) * BN;
    int m0 = bm * BM;
    int tid = threadIdx.x;

    int arow = tid >> 1;
    int acol = (tid & 1) * 4;
    const float* Aptr = g_IN + (m0 + arow) * SIN_ + acol;

    int brow = tid >> 5;
    int bcol = (tid & 31) * 4;
    const float* Bptr = W + brow * 512 + col0 + bcol;

    float4 a0 = *(const float4*)(Aptr);
    float4 b0 = *(const float4*)(Bptr);
    As[0][acol + 0][arow] = a0.x;
    As[0][acol + 1][arow] = a0.y;
    As[0][acol + 2][arow] = a0.z;
    As[0][acol + 3][arow] = a0.w;
    *(float4*)&Bs[0][brow][bcol] = b0;
    __syncthreads();

    float acc[8][8] = {};
    int tx = tid & 15, ty = tid >> 4;

    for (int kt = 1; kt <= 64; kt++) {
        float4 an, bnv;
        if (kt < 64) {
            an  = *(const float4*)(Aptr + kt * BK);
            bnv = *(const float4*)(Bptr + kt * BK * 512);
        }
        int cur = (kt - 1) & 1;
        #pragma unroll
        for (int k = 0; k < BK; k++) {
            float af[8], bf[8];
            *(float4*)(af)     = *(float4*)&As[cur][k][ty * 8];
            *(float4*)(af + 4) = *(float4*)&As[cur][k][ty * 8 + 4];
            *(float4*)(bf)     = *(float4*)&Bs[cur][k][tx * 8];
            *(float4*)(bf + 4) = *(float4*)&Bs[cur][k][tx * 8 + 4];
            #pragma unroll
            for (int i = 0; i < 8; i++)
                #pragma unroll
                for (int j = 0; j < 8; j++) acc[i][j] += af[i] * bf[j];
        }
        if (kt < 64) {
            int nxt = kt & 1;
            As[nxt][acol + 0][arow] = an.x;
            As[nxt][acol + 1][arow] = an.y;
            As[nxt][acol + 2][arow] = an.z;
            As[nxt][acol + 3][arow] = an.w;
            *(float4*)&Bs[nxt][brow][bcol] = bnv;
            __syncthreads();
        }
    }

    int n0 = bn * BN;
    #pragma unroll
    for (int i = 0; i < 8; i++) {
        int row = m0 + ty * 8 + i;
        float* Cp = &g_U[row * UN_ + n0 + tx * 8];
        *(float4*)(Cp)     = make_float4(acc[i][0], acc[i][1], acc[i][2], acc[i][3]);
        *(float4*)(Cp + 4) = make_float4(acc[i][4], acc[i][5], acc[i][6], acc[i][7]);
    }
}

__global__ void __launch_bounds__(128) k_scan(const float* __restrict__ biasf,
                                              const float* __restrict__ biasb,
                                              float* __restrict__ outp,
                                              int final_mode) {
    const int CH = 8;
    int b = blockIdx.x, dir = blockIdx.y;
    int h = threadIdx.x;
    const float* bias = dir ? biasb : biasf;
    float bfv = bias[h];
    float brv = bias[H_ + h];
    __shared__ float buf[2][CH][512];
    const float* Ub = g_U + b * UN_ + dir * 512;

    float4 pre[CH];
    #pragma unroll
    for (int st = 0; st < CH; st++)
        pre[st] = *(const float4*)(Ub + st * (B_ * UN_) + h * 4);
    #pragma unroll
    for (int st = 0; st < CH; st++)
        *(float4*)&buf[0][st][h * 4] = pre[st];
    __syncthreads();

    float c = 0.0f;
    for (int ck = 0; ck < S_ / CH; ck++) {
        int cur = ck & 1;
        if (ck + 1 < S_ / CH) {
            const float* Un = Ub + (ck + 1) * CH * (B_ * UN_);
            #pragma unroll
            for (int st = 0; st < CH; st++)
                pre[st] = *(const float4*)(Un + st * (B_ * UN_) + h * 4);
        }
        #pragma unroll
        for (int st = 0; st < CH; st++) {
            int s = ck * CH + st;
            float u0 = buf[cur][st][h];
            float uf = buf[cur][st][128 + h];
            float ur = buf[cur][st][256 + h];
            float hw = buf[cur][st][384 + h];
            float f = sigm(uf + bfv);
            float r = sigm(ur + brv);
            c = f * c + (1.0f - f) * u0;
            float hv = r * tanh_acc(c) + (1.0f - r) * hw;
            if (final_mode) outp[(b * S_ + s) * D_ + dir * H_ + h] = hv;
            else            g_IN[(s * B_ + b) * SIN_ + dir * H_ + h] = hv;
        }
        __syncthreads();
        if (ck + 1 < S_ / CH) {
            int nxt = (ck + 1) & 1;
            #pragma unroll
            for (int st = 0; st < CH; st++)
                *(float4*)&buf[nxt][st][h * 4] = pre[st];
        }
        __syncthreads();
    }
}

extern "C" void kernel_launch(void* const* d_in, const int* in_sizes, int n_in,
                              void* d_out, int out_size) {
    (void)in_sizes; (void)n_in; (void)out_size;
    const float* x       = (const float*)d_in[0];
    const int*   actions = (const int*)d_in[2];
    const float* w1      = (const float*)d_in[3];
    const float* b1      = (const float*)d_in[4];
    const float* w2      = (const float*)d_in[5];
    const float* b2      = (const float*)d_in[6];
    const float* v       = (const float*)d_in[7];
    const float* swf     = (const float*)d_in[8];
    const float* sbf     = (const float*)d_in[9];
    const float* swb     = (const float*)d_in[10];
    const float* sbb     = (const float*)d_in[11];
    float* out = (float*)d_out;

    k_init<<<(S_ * B_ * D_) / 256, 256>>>(x);
    k_projXT<<<dim3(4, 16), 256>>>(x, actions, w1, b1);
    for (int layer = 0; layer < 2; layer++) {
        k_projYT<<<dim3(4, 16), 256>>>(actions, w2, b2);
        k_attn<<<256, 256>>>(x, actions, v);
        k_sgemm<<<dim3(8, 32), 256>>>(swf + layer * SIN_ * 512,
                                      swb + layer * SIN_ * 512);
        k_scan<<<dim3(16, 2), 128>>>(sbf + layer * 2 * H_,
                                     sbb + layer * 2 * H_,
                                     out, (layer == 1) ? 1 : 0);
    }
}

// round 11
// speedup vs baseline: 1.0684x; 1.0684x over previous
#include <cuda_runtime.h>

#define DI __device__ __forceinline__
typedef unsigned long long ull;

#define B_   16
#define S_   256
#define D_   256
#define H_   128
#define DK_  64
#define SIN_ 512
#define UN_  1024
#define M_   4096

__device__ float g_XT[B_ * DK_ * S_];   // [b][k][l]
__device__ float g_YT[M_ * DK_];        // [(s*B+b)][k]
__device__ float g_IN[M_ * SIN_];       // [(s*B+b)][0:256]=out, [256:512]=pools
__device__ float g_U [M_ * UN_];        // [(s*B+b)][dir*512 + slice*128 + h]

DI float tanhf_a(float x) {            // MUFU.TANH, 1 op (attention only)
    float y;
    asm("tanh.approx.f32 %0, %1;" : "=f"(y) : "f"(x));
    return y;
}
// accurate versions (scan path — accuracy-critical)
DI float tanh_acc(float x) {
    float e = __expf(2.0f * x);
    return 1.0f - __fdividef(2.0f, e + 1.0f);
}
DI float sigm_acc(float x) {
    return __fdividef(1.0f, 1.0f + __expf(-x));
}
DI void fma2(float2& d, float2 a, float2 b) {   // packed fp32x2 FMA (Blackwell)
    asm("fma.rn.f32x2 %0, %1, %2, %0;"
        : "+l"(*reinterpret_cast<ull*>(&d))
        : "l"(*reinterpret_cast<const ull*>(&a)),
          "l"(*reinterpret_cast<const ull*>(&b)));
}

__global__ void k_init(const float* __restrict__ x) {
    int i = blockIdx.x * blockDim.x + threadIdx.x;
    int d  = i & (D_ - 1);
    int sb = i >> 8;
    int b  = sb & (B_ - 1);
    int s  = sb >> 4;
    g_IN[(s * B_ + b) * SIN_ + d] = x[(b * S_ + s) * D_ + d];
}

__global__ void __launch_bounds__(256) k_projXT(const float* __restrict__ x,
                                                const int* __restrict__ actions,
                                                const float* __restrict__ w1,
                                                const float* __restrict__ b1) {
    int b  = blockIdx.y;
    int l0 = blockIdx.x * 64;
    int a  = actions[b];
    const float* W = w1 + a * D_ * DK_;
    const float* X = x + (b * S_ + l0) * D_;
    __shared__ float Xs[64][64];
    __shared__ float Ws[64][64];
    int tid = threadIdx.x;
    int tx = tid & 15, ty = tid >> 4;
    float acc[4][4] = {};
    for (int dc = 0; dc < 4; dc++) {
        #pragma unroll
        for (int p = 0; p < 4; p++) {
            int r  = (tid >> 4) + p * 16;
            int cc = (tid & 15) * 4;
            *(float4*)&Xs[r][cc] = *(const float4*)(X + r * D_ + dc * 64 + cc);
            *(float4*)&Ws[r][cc] = *(const float4*)(W + (dc * 64 + r) * DK_ + cc);
        }
        __syncthreads();
        #pragma unroll
        for (int dd = 0; dd < 64; dd++) {
            float av[4], bv[4];
            #pragma unroll
            for (int i = 0; i < 4; i++) av[i] = Xs[ty * 4 + i][dd];
            *(float4*)bv = *(float4*)&Ws[dd][tx * 4];
            #pragma unroll
            for (int i = 0; i < 4; i++)
                #pragma unroll
                for (int j = 0; j < 4; j++) acc[i][j] += av[i] * bv[j];
        }
        __syncthreads();
    }
    #pragma unroll
    for (int j = 0; j < 4; j++) {
        int k = tx * 4 + j;
        float bb = b1[a * DK_ + k];
        #pragma unroll
        for (int i = 0; i < 4; i++) {
            int l = l0 + ty * 4 + i;
            g_XT[(b * DK_ + k) * S_ + l] = acc[i][j] + bb;
        }
    }
}

__global__ void __launch_bounds__(256) k_projYT(const int* __restrict__ actions,
                                                const float* __restrict__ w2,
                                                const float* __restrict__ b2) {
    int b  = blockIdx.y;
    int s0 = blockIdx.x * 64;
    int a  = actions[b];
    const float* W = w2 + a * D_ * DK_;
    __shared__ float Xs[64][64];
    __shared__ float Ws[64][64];
    int tid = threadIdx.x;
    int tx = tid & 15, ty = tid >> 4;
    float acc[4][4] = {};
    for (int dc = 0; dc < 4; dc++) {
        #pragma unroll
        for (int p = 0; p < 4; p++) {
            int r  = (tid >> 4) + p * 16;
            int cc = (tid & 15) * 4;
            *(float4*)&Xs[r][cc] =
                *(const float4*)(&g_IN[((s0 + r) * B_ + b) * SIN_ + dc * 64 + cc]);
            *(float4*)&Ws[r][cc] = *(const float4*)(W + (dc * 64 + r) * DK_ + cc);
        }
        __syncthreads();
        #pragma unroll
        for (int dd = 0; dd < 64; dd++) {
            float av[4], bv[4];
            #pragma unroll
            for (int i = 0; i < 4; i++) av[i] = Xs[ty * 4 + i][dd];
            *(float4*)bv = *(float4*)&Ws[dd][tx * 4];
            #pragma unroll
            for (int i = 0; i < 4; i++)
                #pragma unroll
                for (int j = 0; j < 4; j++) acc[i][j] += av[i] * bv[j];
        }
        __syncthreads();
    }
    #pragma unroll
    for (int j = 0; j < 4; j++) {
        int k = tx * 4 + j;
        float bb = b2[a * DK_ + k];
        #pragma unroll
        for (int i = 0; i < 4; i++) {
            int s = s0 + ty * 4 + i;
            g_YT[(s * B_ + b) * DK_ + k] = acc[i][j] + bb;
        }
    }
}

// fused attention; G=8 timesteps per block; grid = 16 b * 32 groups = 512 blocks
__global__ void __launch_bounds__(256) k_attn(const float* __restrict__ x,
                                              const int* __restrict__ actions,
                                              const float* __restrict__ v) {
    const int G = 8;
    int b  = blockIdx.x & (B_ - 1);
    int s0 = (blockIdx.x >> 4) * G;
    int tid = threadIdx.x;
    int a = actions[b];
    __shared__ __align__(16) float yt[G][DK_];
    __shared__ __align__(16) float att[G][S_];
    __shared__ float vv[DK_];
    __shared__ float inv[G];
    for (int i = tid; i < G * DK_; i += 256) {
        int g = i >> 6, k = i & 63;
        yt[g][k] = g_YT[((s0 + g) * B_ + b) * DK_ + k];
    }
    if (tid < DK_) vv[tid] = v[a * DK_ + tid];
    __syncthreads();

    const float* xtp = g_XT + b * DK_ * S_;
    float sc[G];
    #pragma unroll
    for (int g = 0; g < G; g++) sc[g] = 0.0f;
    int l = tid;
    for (int k = 0; k < DK_; k++) {
        float xt = xtp[k * S_ + l];
        float vk = vv[k];
        #pragma unroll
        for (int g = 0; g < G; g++)
            sc[g] += tanhf_a(xt + yt[g][k]) * vk;
    }
    #pragma unroll
    for (int g = 0; g < G; g++) att[g][l] = sc[g];
    __syncthreads();

    // softmax: warp w handles group g = w
    int g = tid >> 5, lane = tid & 31;
    {
        float m = -1e30f;
        #pragma unroll
        for (int j = 0; j < 8; j++) m = fmaxf(m, att[g][lane * 8 + j]);
        #pragma unroll
        for (int o = 16; o > 0; o >>= 1) m = fmaxf(m, __shfl_xor_sync(0xffffffffu, m, o));
        float ssum = 0.0f;
        #pragma unroll
        for (int j = 0; j < 8; j++) {
            float e = __expf(att[g][lane * 8 + j] - m);
            att[g][lane * 8 + j] = e;
            ssum += e;
        }
        #pragma unroll
        for (int o = 16; o > 0; o >>= 1) ssum += __shfl_xor_sync(0xffffffffu, ssum, o);
        if (lane == 0) inv[g] = __fdividef(1.0f, ssum);
    }
    __syncthreads();

    float acc[G];
    #pragma unroll
    for (int gg = 0; gg < G; gg++) acc[gg] = 0.0f;
    const float* xb = x + b * S_ * D_;
    int d = tid;
    for (int l2 = 0; l2 < S_; l2 += 4) {
        float xv0 = xb[(l2 + 0) * D_ + d];
        float xv1 = xb[(l2 + 1) * D_ + d];
        float xv2 = xb[(l2 + 2) * D_ + d];
        float xv3 = xb[(l2 + 3) * D_ + d];
        #pragma unroll
        for (int gg = 0; gg < G; gg++) {
            float4 av = *reinterpret_cast<const float4*>(&att[gg][l2]);
            acc[gg] += av.x * xv0 + av.y * xv1 + av.z * xv2 + av.w * xv3;
        }
    }
    #pragma unroll
    for (int gg = 0; gg < G; gg++)
        g_IN[((s0 + gg) * B_ + b) * SIN_ + D_ + d] = acc[gg] * inv[gg];
}

// SGEMM g_U = g_IN (4096x512) x W (512x1024), packed f32x2 FMA path
__global__ void __launch_bounds__(256, 2) k_sgemm(const float* __restrict__ wf,
                                                  const float* __restrict__ wb) {
    const int BM = 128, BN = 128, BK = 8;
    __shared__ float As[2][BK][BM];
    __shared__ float Bs[2][BK][BN];
    int bn = blockIdx.x, bm = blockIdx.y;
    const float* W = (bn < 4) ? wf : wb;
    int col0 = (bn & 3) * BN;
    int m0 = bm * BM;
    int tid = threadIdx.x;

    int arow = tid >> 1;
    int acol = (tid & 1) * 4;
    const float* Aptr = g_IN + (m0 + arow) * SIN_ + acol;

    int brow = tid >> 5;
    int bcol = (tid & 31) * 4;
    const float* Bptr = W + brow * 512 + col0 + bcol;

    float4 a0 = *(const float4*)(Aptr);
    float4 b0 = *(const float4*)(Bptr);
    As[0][acol + 0][arow] = a0.x;
    As[0][acol + 1][arow] = a0.y;
    As[0][acol + 2][arow] = a0.z;
    As[0][acol + 3][arow] = a0.w;
    *(float4*)&Bs[0][brow][bcol] = b0;
    __syncthreads();

    float2 acc[4][8];   // acc[p][j]: rows (ty*8+2p, ty*8+2p+1), col tx*8+j
    #pragma unroll
    for (int p = 0; p < 4; p++)
        #pragma unroll
        for (int j = 0; j < 8; j++) acc[p][j] = make_float2(0.0f, 0.0f);

    int tx = tid & 15, ty = tid >> 4;

    for (int kt = 1; kt <= 64; kt++) {
        float4 an, bnv;
        if (kt < 64) {
            an  = *(const float4*)(Aptr + kt * BK);
            bnv = *(const float4*)(Bptr + kt * BK * 512);
        }
        int cur = (kt - 1) & 1;
        #pragma unroll
        for (int k = 0; k < BK; k++) {
            float2 a2[4];
            #pragma unroll
            for (int p = 0; p < 4; p++)
                a2[p] = *(const float2*)&As[cur][k][ty * 8 + 2 * p];
            float bf[8];
            *(float4*)(bf)     = *(float4*)&Bs[cur][k][tx * 8];
            *(float4*)(bf + 4) = *(float4*)&Bs[cur][k][tx * 8 + 4];
            #pragma unroll
            for (int j = 0; j < 8; j++) {
                float2 bd = make_float2(bf[j], bf[j]);
                #pragma unroll
                for (int p = 0; p < 4; p++) fma2(acc[p][j], a2[p], bd);
            }
        }
        if (kt < 64) {
            int nxt = kt & 1;
            As[nxt][acol + 0][arow] = an.x;
            As[nxt][acol + 1][arow] = an.y;
            As[nxt][acol + 2][arow] = an.z;
            As[nxt][acol + 3][arow] = an.w;
            *(float4*)&Bs[nxt][brow][bcol] = bnv;
            __syncthreads();
        }
    }

    int n0 = bn * BN;
    #pragma unroll
    for (int i = 0; i < 8; i++) {
        int row = m0 + ty * 8 + i;
        float vals[8];
        #pragma unroll
        for (int j = 0; j < 8; j++)
            vals[j] = (i & 1) ? acc[i >> 1][j].y : acc[i >> 1][j].x;
        float* Cp = &g_U[row * UN_ + n0 + tx * 8];
        *(float4*)(Cp)     = *(float4*)(vals);
        *(float4*)(Cp + 4) = *(float4*)(vals + 4);
    }
}

__global__ void __launch_bounds__(128) k_scan(const float* __restrict__ biasf,
                                              const float* __restrict__ biasb,
                                              float* __restrict__ outp,
                                              int final_mode) {
    const int CH = 8;
    int b = blockIdx.x, dir = blockIdx.y;
    int h = threadIdx.x;
    const float* bias = dir ? biasb : biasf;
    float bfv = bias[h];
    float brv = bias[H_ + h];
    __shared__ float buf[2][CH][512];
    const float* Ub = g_U + b * UN_ + dir * 512;

    float4 pre[CH];
    #pragma unroll
    for (int st = 0; st < CH; st++)
        pre[st] = *(const float4*)(Ub + st * (B_ * UN_) + h * 4);
    #pragma unroll
    for (int st = 0; st < CH; st++)
        *(float4*)&buf[0][st][h * 4] = pre[st];
    __syncthreads();

    float c = 0.0f;
    for (int ck = 0; ck < S_ / CH; ck++) {
        int cur = ck & 1;
        if (ck + 1 < S_ / CH) {
            const float* Un = Ub + (ck + 1) * CH * (B_ * UN_);
            #pragma unroll
            for (int st = 0; st < CH; st++)
                pre[st] = *(const float4*)(Un + st * (B_ * UN_) + h * 4);
        }
        #pragma unroll
        for (int st = 0; st < CH; st++) {
            int s = ck * CH + st;
            float u0 = buf[cur][st][h];
            float uf = buf[cur][st][128 + h];
            float ur = buf[cur][st][256 + h];
            float hw = buf[cur][st][384 + h];
            float f = sigm_acc(uf + bfv);
            float r = sigm_acc(ur + brv);
            c = f * c + (1.0f - f) * u0;
            float hv = r * tanh_acc(c) + (1.0f - r) * hw;
            if (final_mode) outp[(b * S_ + s) * D_ + dir * H_ + h] = hv;
            else            g_IN[(s * B_ + b) * SIN_ + dir * H_ + h] = hv;
        }
        __syncthreads();
        if (ck + 1 < S_ / CH) {
            int nxt = (ck + 1) & 1;
            #pragma unroll
            for (int st = 0; st < CH; st++)
                *(float4*)&buf[nxt][st][h * 4] = pre[st];
        }
        __syncthreads();
    }
}

extern "C" void kernel_launch(void* const* d_in, const int* in_sizes, int n_in,
                              void* d_out, int out_size) {
    (void)in_sizes; (void)n_in; (void)out_size;
    const float* x       = (const float*)d_in[0];
    const int*   actions = (const int*)d_in[2];
    const float* w1      = (const float*)d_in[3];
    const float* b1      = (const float*)d_in[4];
    const float* w2      = (const float*)d_in[5];
    const float* b2      = (const float*)d_in[6];
    const float* v       = (const float*)d_in[7];
    const float* swf     = (const float*)d_in[8];
    const float* sbf     = (const float*)d_in[9];
    const float* swb     = (const float*)d_in[10];
    const float* sbb     = (const float*)d_in[11];
    float* out = (float*)d_out;

    k_init<<<(S_ * B_ * D_) / 256, 256>>>(x);
    k_projXT<<<dim3(4, 16), 256>>>(x, actions, w1, b1);
    for (int layer = 0; layer < 2; layer++) {
        k_projYT<<<dim3(4, 16), 256>>>(actions, w2, b2);
        k_attn<<<512, 256>>>(x, actions, v);
        k_sgemm<<<dim3(8, 32), 256>>>(swf + layer * SIN_ * 512,
                                      swb + layer * SIN_ * 512);
        k_scan<<<dim3(16, 2), 128>>>(sbf + layer * 2 * H_,
                                     sbb + layer * 2 * H_,
                                     out, (layer == 1) ? 1 : 0);
    }
}